// round 2
// baseline (speedup 1.0000x reference)
#include <cuda_runtime.h>
#include <math.h>

// Problem constants
#define MROWS  16384          // B*N = 32*512
#define DMODEL 512
#define HEADS  8
#define DEPTH  147
#define DH     1176           // HEADS*DEPTH
#define QKC    2352           // 2*DH

// Scratch (static device globals — no runtime allocation)
__device__ float g_QK[(size_t)MROWS * QKC];   // [16384, 2352]  q | k
__device__ float g_V [(size_t)MROWS * DH];    // [16384, 1176]  updated in place by attention

// ---------------------------------------------------------------------------
// SGEMM: C[M,N] = A[M,K] @ B[K,N] (+ bias), row-major everywhere.
// BM=BN=128, BK=8, 256 threads, 8x8 register tile per thread.
// Assumes: M % 128 == 0, K % 8 == 0.
// ---------------------------------------------------------------------------
__global__ __launch_bounds__(256) void sgemm_kernel(
    const float* __restrict__ A, const float* __restrict__ B,
    float* __restrict__ C, int M, int N, int K,
    const float* __restrict__ bias)
{
    constexpr int BM = 128, BN = 128, BK = 8, TM = 8, TN = 8;
    __shared__ float As[BK][BM];
    __shared__ float Bs[BK][BN];

    const int tid  = threadIdx.x;
    const int row0 = blockIdx.y * BM;
    const int col0 = blockIdx.x * BN;
    const int tx = tid & 15;       // 16 cols of threads
    const int ty = tid >> 4;       // 16 rows of threads

    // A tile load mapping: 128 rows x 8 k = 256 float4; one float4 per thread
    const int a_row = tid >> 1;
    const int a_k   = (tid & 1) << 2;
    // B tile load mapping: 8 k x 128 cols = 256 float4
    const int b_k   = tid >> 5;
    const int b_col = (tid & 31) << 2;

    float acc[TM][TN];
    #pragma unroll
    for (int i = 0; i < TM; i++)
        #pragma unroll
        for (int j = 0; j < TN; j++) acc[i][j] = 0.0f;

    const float* Aptr = A + (size_t)(row0 + a_row) * K + a_k;
    const float* Bptr = B + (size_t)b_k * N;
    const int gc = col0 + b_col;
    const bool b_full = (gc + 3 < N);

    for (int k0 = 0; k0 < K; k0 += BK) {
        // A tile (transposed into smem for k-major access)
        float4 av = *(const float4*)(Aptr + k0);
        As[a_k + 0][a_row] = av.x;
        As[a_k + 1][a_row] = av.y;
        As[a_k + 2][a_row] = av.z;
        As[a_k + 3][a_row] = av.w;

        // B tile (guard only the ragged last column-tile)
        const float* Brow = Bptr + (size_t)k0 * N;
        float4 bv;
        if (b_full) {
            bv = *(const float4*)(Brow + gc);
        } else {
            bv = make_float4(0.f, 0.f, 0.f, 0.f);
            if (gc < N)     bv.x = Brow[gc];
            if (gc + 1 < N) bv.y = Brow[gc + 1];
            if (gc + 2 < N) bv.z = Brow[gc + 2];
        }
        *(float4*)&Bs[b_k][b_col] = bv;

        __syncthreads();

        #pragma unroll
        for (int kk = 0; kk < BK; kk++) {
            float ar[TM], br[TN];
            #pragma unroll
            for (int i = 0; i < TM; i++) ar[i] = As[kk][ty * TM + i];
            #pragma unroll
            for (int j = 0; j < TN; j++) br[j] = Bs[kk][tx * TN + j];
            #pragma unroll
            for (int i = 0; i < TM; i++)
                #pragma unroll
                for (int j = 0; j < TN; j++)
                    acc[i][j] = fmaf(ar[i], br[j], acc[i][j]);
        }
        __syncthreads();
    }

    #pragma unroll
    for (int i = 0; i < TM; i++) {
        int r = row0 + ty * TM + i;
        #pragma unroll
        for (int j = 0; j < TN; j++) {
            int c = col0 + tx * TN + j;
            if (c < N) {
                float v = acc[i][j];
                if (bias) v += bias[c];
                C[(size_t)r * N + c] = v;
            }
        }
    }
}

// ---------------------------------------------------------------------------
// Tiny per-frame attention: one warp per (m, h) unit, 8 warps per block.
// Reads q,k from g_QK and v from g_V; rewrites g_V[m, h*147+3 .. h*147+146]
// in place (dims 0..2 pass through untouched).
// ---------------------------------------------------------------------------
__global__ __launch_bounds__(256) void attn_kernel(
    const float* __restrict__ QK, float* __restrict__ V)
{
    const int warp = threadIdx.x >> 5;
    const int lane = threadIdx.x & 31;
    const int f = blockIdx.x * 8 + warp;      // 0 .. MROWS*HEADS-1
    const int m = f >> 3;
    const int h = f & 7;

    __shared__ float sq[8][144];
    __shared__ float sk[8][144];
    __shared__ float sv[8][144];
    __shared__ float sp[8][24][25];           // padded scores/probs

    float* q = sq[warp];
    float* k = sk[warp];
    float* v = sv[warp];
    float (*p)[25] = sp[warp];

    const float* qrow = QK + (size_t)m * QKC + h * DEPTH + 3;
    const float* krow = QK + (size_t)m * QKC + DH + h * DEPTH + 3;
    float*       vrow = V  + (size_t)m * DH  + h * DEPTH + 3;

    for (int i = lane; i < 144; i += 32) {
        q[i] = qrow[i];
        k[i] = krow[i];
        v[i] = vrow[i];
    }
    __syncwarp();

    // scores[r][c] = (qa_r . ka_c) / sqrt(6)
    const float scale = 0.4082482904638630f;  // 1/sqrt(6)
    for (int e = lane; e < 576; e += 32) {
        int r = e / 24, c = e % 24;
        float s = 0.f;
        #pragma unroll
        for (int d = 0; d < 6; d++) s = fmaf(q[r * 6 + d], k[c * 6 + d], s);
        p[r][c] = s * scale;
    }
    __syncwarp();

    // row softmax (lanes 0..23 each own a row)
    if (lane < 24) {
        float mx = -1e30f;
        #pragma unroll
        for (int c = 0; c < 24; c++) mx = fmaxf(mx, p[lane][c]);
        float sum = 0.f;
        #pragma unroll
        for (int c = 0; c < 24; c++) {
            float e = __expf(p[lane][c] - mx);
            p[lane][c] = e;
            sum += e;
        }
        float inv = 1.0f / sum;
        #pragma unroll
        for (int c = 0; c < 24; c++) p[lane][c] *= inv;
    }
    __syncwarp();

    // sequential averaging chain (exact reference order), lane 0 only
    if (lane == 0) {
        p[0][6]  = (p[0][6]  + p[0][3])  * 0.5f;
        p[6][0]  = (p[6][0]  + p[3][0])  * 0.5f;
        p[0][9]  = (p[0][9]  + p[0][6])  * 0.5f;
        p[9][0]  = (p[9][0]  + p[6][0])  * 0.5f;
        p[0][12] = (p[0][12] + p[0][9])  * 0.5f;
        p[12][0] = (p[12][0] + p[9][0])  * 0.5f;
        p[0][13] = (p[0][13] + p[0][9])  * 0.5f;
        p[13][0] = (p[13][0] + p[9][0])  * 0.5f;
        p[0][14] = (p[0][14] + p[0][9])  * 0.5f;
        p[14][0] = (p[14][0] + p[9][0])  * 0.5f;
        p[0][16] = (p[0][16] + p[0][13]) * 0.5f;
        p[16][0] = (p[16][0] + p[13][0]) * 0.5f;
        p[0][17] = (p[0][17] + p[0][14]) * 0.5f;
        p[17][0] = (p[17][0] + p[14][0]) * 0.5f;
        p[0][15] = (p[0][15] + p[0][12]) * 0.5f;
        p[15][0] = (p[15][0] + p[12][0]) * 0.5f;
    }
    __syncwarp();

    // attn = probs @ va, written back in place
    for (int e = lane; e < 144; e += 32) {
        int r = e / 6, d = e % 6;
        float s = 0.f;
        #pragma unroll
        for (int kk = 0; kk < 24; kk++) s = fmaf(p[r][kk], v[kk * 6 + d], s);
        vrow[e] = s;
    }
}

// ---------------------------------------------------------------------------
// Entry point
// ---------------------------------------------------------------------------
extern "C" void kernel_launch(void* const* d_in, const int* in_sizes, int n_in,
                              void* d_out, int out_size)
{
    const float* query = (const float*)d_in[0];
    // d_in[1] = key: intentionally unused (reference ignores it)
    const float* value = (const float*)d_in[2];
    const float* qk_w  = (const float*)d_in[3];
    const float* v_w   = (const float*)d_in[4];
    const float* lin_w = (const float*)d_in[5];
    const float* lin_b = (const float*)d_in[6];
    float* out = (float*)d_out;

    // One-time symbol lookup (host-side, not stream work; cached so the
    // capture path is pure kernel launches).
    static float* QK = nullptr;
    static float* V  = nullptr;
    if (!QK) {
        cudaGetSymbolAddress((void**)&QK, g_QK);
        cudaGetSymbolAddress((void**)&V,  g_V);
    }

    dim3 blk(256);

    // GEMM1: QK = query @ qk_w     [16384,512] @ [512,2352]
    sgemm_kernel<<<dim3((QKC + 127) / 128, MROWS / 128), blk>>>(
        query, qk_w, QK, MROWS, QKC, DMODEL, nullptr);

    // GEMM2: V = value @ v_w       [16384,512] @ [512,1176]
    sgemm_kernel<<<dim3((DH + 127) / 128, MROWS / 128), blk>>>(
        value, v_w, V, MROWS, DH, DMODEL, nullptr);

    // Tiny attention, in-place update of V (one warp per (m,h))
    attn_kernel<<<(MROWS * HEADS) / 8, 256>>>(QK, V);

    // GEMM3: out = V @ lin_w + lin_b   [16384,1176] @ [1176,512]
    sgemm_kernel<<<dim3(DMODEL / 128, MROWS / 128), blk>>>(
        V, lin_w, out, MROWS, DMODEL, DH, lin_b);
}

// round 3
// speedup vs baseline: 2.4692x; 2.4692x over previous
#include <cuda_runtime.h>
#include <math.h>

// Problem constants
#define MROWS   16384          // B*N = 32*512
#define DMODEL  512
#define HEADS   8
#define DEPTH   147
#define DH      1176           // HEADS*DEPTH
#define QKC     2352           // 2*DH
#define VSTRIDE 1184           // DH padded up to a multiple of 16 (for GEMM3 K-loop)

// Scratch (static device globals — no runtime allocation)
__device__ float g_QK[(size_t)MROWS * QKC];      // [16384, 2352]  q | k
__device__ float g_V [(size_t)MROWS * VSTRIDE];  // [16384, 1184]  cols 1176..1183 are zeros

__device__ __forceinline__ unsigned f2tf(float x) {
    unsigned r;
    asm("cvt.rna.tf32.f32 %0, %1;" : "=r"(r) : "f"(x));
    return r;
}

// ---------------------------------------------------------------------------
// TF32 tensor-core GEMM: C[M,N] = A[M,K] @ B[K,N] (+ bias)
// Tile 128x128x16, 256 threads (8 warps, 2x4), warp tile 64x32 via m16n8k8.
// K must be a multiple of 16 (caller pads); A reads are always in-bounds.
// B guarded by (k < KB) && (col < NB); C stores guarded by col < Nstore.
// ---------------------------------------------------------------------------
__global__ __launch_bounds__(256, 2) void tf32_gemm_kernel(
    const float* __restrict__ A, const float* __restrict__ B,
    float* __restrict__ C, const float* __restrict__ bias,
    int K, int lda, int ldb, int ldc,
    int NB, int KB, int Nstore)
{
    constexpr int BM = 128, BN = 128, BK = 16;
    constexpr int ASTR = 20;    // 16 + 4 pad : stride ≡ 20 (mod 32) -> conflict-free frags
    constexpr int BSTR = 136;   // 128 + 8 pad: stride ≡ 8  (mod 32) -> conflict-free frags
    __shared__ unsigned As[2][BM * ASTR];
    __shared__ unsigned Bs[2][BK * BSTR];

    const int tid  = threadIdx.x;
    const int wid  = tid >> 5;
    const int lane = tid & 31;
    const int gp   = lane >> 2;          // groupID (0..7)
    const int tg   = lane & 3;           // thread-in-group (0..3)
    const int warp_m = (wid & 1) * 64;
    const int warp_n = (wid >> 1) * 32;

    const int row0 = blockIdx.y * BM;
    const int col0 = blockIdx.x * BN;

    float4 pa[2], pb[2];                 // prefetch registers

    auto ldg_tile = [&](int k0) {
        #pragma unroll
        for (int i = 0; i < 2; i++) {
            int t = tid + i * 256;
            // A: 128 rows x 4 float4 (16 k)
            int arow = t >> 2, akq = t & 3;
            pa[i] = *(const float4*)(A + (size_t)(row0 + arow) * lda + k0 + akq * 4);
            // B: 16 k-rows x 32 float4 (128 cols)
            int bkr = t >> 5, bcq = t & 31;
            int gk = k0 + bkr, gc = col0 + bcq * 4;
            float4 v = make_float4(0.f, 0.f, 0.f, 0.f);
            if (gk < KB) {
                const float* p = B + (size_t)gk * ldb;
                if (gc + 3 < NB) {
                    v = *(const float4*)(p + gc);
                } else {
                    if (gc     < NB) v.x = p[gc];
                    if (gc + 1 < NB) v.y = p[gc + 1];
                    if (gc + 2 < NB) v.z = p[gc + 2];
                }
            }
            pb[i] = v;
        }
    };

    auto sts_tile = [&](int buf) {
        #pragma unroll
        for (int i = 0; i < 2; i++) {
            int t = tid + i * 256;
            int arow = t >> 2, akq = t & 3;
            unsigned* d = &As[buf][arow * ASTR + akq * 4];
            d[0] = f2tf(pa[i].x); d[1] = f2tf(pa[i].y);
            d[2] = f2tf(pa[i].z); d[3] = f2tf(pa[i].w);
            int bkr = t >> 5, bcq = t & 31;
            unsigned* e = &Bs[buf][bkr * BSTR + bcq * 4];
            e[0] = f2tf(pb[i].x); e[1] = f2tf(pb[i].y);
            e[2] = f2tf(pb[i].z); e[3] = f2tf(pb[i].w);
        }
    };

    float acc[4][4][4];
    #pragma unroll
    for (int mt = 0; mt < 4; mt++)
        #pragma unroll
        for (int nt = 0; nt < 4; nt++)
            #pragma unroll
            for (int r = 0; r < 4; r++) acc[mt][nt][r] = 0.f;

    ldg_tile(0);
    sts_tile(0);
    __syncthreads();

    int buf = 0;
    for (int k0 = 0; k0 < K; k0 += BK) {
        const bool more = (k0 + BK) < K;
        if (more) ldg_tile(k0 + BK);

        #pragma unroll
        for (int ks = 0; ks < 2; ks++) {
            unsigned af[4][4], bf[4][2];
            #pragma unroll
            for (int mt = 0; mt < 4; mt++) {
                int base = (warp_m + mt * 16 + gp) * ASTR + ks * 8 + tg;
                af[mt][0] = As[buf][base];
                af[mt][1] = As[buf][base + 8 * ASTR];
                af[mt][2] = As[buf][base + 4];
                af[mt][3] = As[buf][base + 8 * ASTR + 4];
            }
            #pragma unroll
            for (int nt = 0; nt < 4; nt++) {
                int base = (ks * 8 + tg) * BSTR + warp_n + nt * 8 + gp;
                bf[nt][0] = Bs[buf][base];
                bf[nt][1] = Bs[buf][base + 4 * BSTR];
            }
            #pragma unroll
            for (int mt = 0; mt < 4; mt++)
                #pragma unroll
                for (int nt = 0; nt < 4; nt++) {
                    asm volatile(
                        "mma.sync.aligned.m16n8k8.row.col.f32.tf32.tf32.f32 "
                        "{%0,%1,%2,%3}, {%4,%5,%6,%7}, {%8,%9}, {%0,%1,%2,%3};"
                        : "+f"(acc[mt][nt][0]), "+f"(acc[mt][nt][1]),
                          "+f"(acc[mt][nt][2]), "+f"(acc[mt][nt][3])
                        : "r"(af[mt][0]), "r"(af[mt][1]),
                          "r"(af[mt][2]), "r"(af[mt][3]),
                          "r"(bf[nt][0]), "r"(bf[nt][1]));
                }
        }

        if (more) sts_tile(buf ^ 1);
        __syncthreads();
        buf ^= 1;
    }

    // Epilogue: c0,c1 -> (row gp, cols 2tg,2tg+1); c2,c3 -> row gp+8
    const bool full = (col0 + BN) <= Nstore;
    #pragma unroll
    for (int mt = 0; mt < 4; mt++) {
        #pragma unroll
        for (int half = 0; half < 2; half++) {
            int r = row0 + warp_m + mt * 16 + gp + half * 8;
            float* crow = C + (size_t)r * ldc;
            #pragma unroll
            for (int nt = 0; nt < 4; nt++) {
                int c  = col0 + warp_n + nt * 8 + tg * 2;
                float v0 = acc[mt][nt][half * 2 + 0];
                float v1 = acc[mt][nt][half * 2 + 1];
                if (full) {
                    if (bias) { v0 += bias[c]; v1 += bias[c + 1]; }
                    float2 st = make_float2(v0, v1);
                    *(float2*)(crow + c) = st;
                } else {
                    if (c < Nstore) {
                        if (bias) v0 += bias[c];
                        crow[c] = v0;
                    }
                    if (c + 1 < Nstore) {
                        if (bias) v1 += bias[c + 1];
                        crow[c + 1] = v1;
                    }
                }
            }
        }
    }
}

// ---------------------------------------------------------------------------
// Tiny per-frame attention: one warp per (m, h) unit, 8 warps per block.
// In-place update of g_V[m, h*147+3 .. h*147+146] (dims 0..2 untouched).
// ---------------------------------------------------------------------------
__global__ __launch_bounds__(256) void attn_kernel(
    const float* __restrict__ QK, float* __restrict__ V)
{
    const int warp = threadIdx.x >> 5;
    const int lane = threadIdx.x & 31;
    const int f = blockIdx.x * 8 + warp;
    const int m = f >> 3;
    const int h = f & 7;

    __shared__ float sq[8][144];
    __shared__ float sk[8][144];
    __shared__ float sv[8][144];
    __shared__ float sp[8][24][25];

    float* q = sq[warp];
    float* k = sk[warp];
    float* v = sv[warp];
    float (*p)[25] = sp[warp];

    const float* qrow = QK + (size_t)m * QKC + h * DEPTH + 3;
    const float* krow = QK + (size_t)m * QKC + DH + h * DEPTH + 3;
    float*       vrow = V  + (size_t)m * VSTRIDE + h * DEPTH + 3;

    for (int i = lane; i < 144; i += 32) {
        q[i] = qrow[i];
        k[i] = krow[i];
        v[i] = vrow[i];
    }
    __syncwarp();

    const float scale = 0.4082482904638630f;  // 1/sqrt(6)
    for (int e = lane; e < 576; e += 32) {
        int r = e / 24, c = e % 24;
        float s = 0.f;
        #pragma unroll
        for (int d = 0; d < 6; d++) s = fmaf(q[r * 6 + d], k[c * 6 + d], s);
        p[r][c] = s * scale;
    }
    __syncwarp();

    if (lane < 24) {
        float mx = -1e30f;
        #pragma unroll
        for (int c = 0; c < 24; c++) mx = fmaxf(mx, p[lane][c]);
        float sum = 0.f;
        #pragma unroll
        for (int c = 0; c < 24; c++) {
            float e = __expf(p[lane][c] - mx);
            p[lane][c] = e;
            sum += e;
        }
        float inv = 1.0f / sum;
        #pragma unroll
        for (int c = 0; c < 24; c++) p[lane][c] *= inv;
    }
    __syncwarp();

    if (lane == 0) {
        p[0][6]  = (p[0][6]  + p[0][3])  * 0.5f;
        p[6][0]  = (p[6][0]  + p[3][0])  * 0.5f;
        p[0][9]  = (p[0][9]  + p[0][6])  * 0.5f;
        p[9][0]  = (p[9][0]  + p[6][0])  * 0.5f;
        p[0][12] = (p[0][12] + p[0][9])  * 0.5f;
        p[12][0] = (p[12][0] + p[9][0])  * 0.5f;
        p[0][13] = (p[0][13] + p[0][9])  * 0.5f;
        p[13][0] = (p[13][0] + p[9][0])  * 0.5f;
        p[0][14] = (p[0][14] + p[0][9])  * 0.5f;
        p[14][0] = (p[14][0] + p[9][0])  * 0.5f;
        p[0][16] = (p[0][16] + p[0][13]) * 0.5f;
        p[16][0] = (p[16][0] + p[13][0]) * 0.5f;
        p[0][17] = (p[0][17] + p[0][14]) * 0.5f;
        p[17][0] = (p[17][0] + p[14][0]) * 0.5f;
        p[0][15] = (p[0][15] + p[0][12]) * 0.5f;
        p[15][0] = (p[15][0] + p[12][0]) * 0.5f;
    }
    __syncwarp();

    for (int e = lane; e < 144; e += 32) {
        int r = e / 6, d = e % 6;
        float s = 0.f;
        #pragma unroll
        for (int kk = 0; kk < 24; kk++) s = fmaf(p[r][kk], v[kk * 6 + d], s);
        vrow[e] = s;
    }
}

// ---------------------------------------------------------------------------
// Entry point
// ---------------------------------------------------------------------------
extern "C" void kernel_launch(void* const* d_in, const int* in_sizes, int n_in,
                              void* d_out, int out_size)
{
    const float* query = (const float*)d_in[0];
    // d_in[1] = key: intentionally unused (reference ignores it)
    const float* value = (const float*)d_in[2];
    const float* qk_w  = (const float*)d_in[3];
    const float* v_w   = (const float*)d_in[4];
    const float* lin_w = (const float*)d_in[5];
    const float* lin_b = (const float*)d_in[6];
    float* out = (float*)d_out;

    static float* QK = nullptr;
    static float* V  = nullptr;
    if (!QK) {
        cudaGetSymbolAddress((void**)&QK, g_QK);
        cudaGetSymbolAddress((void**)&V,  g_V);
    }

    dim3 blk(256);

    // GEMM1: QK = query @ qk_w   [16384,512]@[512,2352], N ragged (19 tiles)
    tf32_gemm_kernel<<<dim3(19, MROWS / 128), blk>>>(
        query, qk_w, QK, nullptr,
        /*K=*/512, /*lda=*/512, /*ldb=*/QKC, /*ldc=*/QKC,
        /*NB=*/QKC, /*KB=*/512, /*Nstore=*/QKC);

    // GEMM2: V = value @ v_w     [16384,512]@[512,1176] -> padded [.,1184]
    // (cols 1176..1183 get exact zeros via the NB guard)
    tf32_gemm_kernel<<<dim3(10, MROWS / 128), blk>>>(
        value, v_w, V, nullptr,
        /*K=*/512, /*lda=*/512, /*ldb=*/DH, /*ldc=*/VSTRIDE,
        /*NB=*/DH, /*KB=*/512, /*Nstore=*/VSTRIDE);

    // Tiny attention, in-place update of V (one warp per (m,h))
    attn_kernel<<<(MROWS * HEADS) / 8, 256>>>(QK, V);

    // GEMM3: out = V @ lin_w + b [16384,1184(pad)]@[1176,512]
    // (K padded to 1184; A pad cols are zero, B rows >=1176 guarded to zero)
    tf32_gemm_kernel<<<dim3(4, MROWS / 128), blk>>>(
        V, lin_w, out, lin_b,
        /*K=*/VSTRIDE, /*lda=*/VSTRIDE, /*ldb=*/DMODEL, /*ldc=*/DMODEL,
        /*NB=*/DMODEL, /*KB=*/DH, /*Nstore=*/DMODEL);
}

// round 6
// speedup vs baseline: 2.9766x; 1.2055x over previous
#include <cuda_runtime.h>
#include <math.h>

// Problem constants
#define MROWS   16384          // B*N = 32*512
#define DMODEL  512
#define HEADS   8
#define DEPTH   147
#define DH      1176           // HEADS*DEPTH
#define QKC     2352           // 2*DH
#define VSTRIDE 1184           // DH padded to multiple of 16 (GEMM3 K-loop)

// Scratch (static device globals — no runtime allocation)
__device__ float g_QK[(size_t)MROWS * QKC];      // [16384, 2352]  q | k
__device__ float g_V [(size_t)MROWS * VSTRIDE];  // [16384, 1184]  cols 1176..1183 zero

__device__ __forceinline__ unsigned f2tf(float x) {
    unsigned r;
    asm("cvt.rna.tf32.f32 %0, %1;" : "=r"(r) : "f"(x));
    return r;
}
__device__ __forceinline__ unsigned smem_u32(const void* p) {
    return (unsigned)__cvta_generic_to_shared(p);
}
#define CP_ASYNC16(dst_u32, src_ptr, bytes) \
    asm volatile("cp.async.cg.shared.global [%0], [%1], 16, %2;" \
                 :: "r"(dst_u32), "l"(src_ptr), "r"(bytes))
#define CP_COMMIT()  asm volatile("cp.async.commit_group;")
#define CP_WAIT(n)   asm volatile("cp.async.wait_group %0;" :: "n"(n))

// ---------------------------------------------------------------------------
// TF32 tensor-core GEMM body: C[M,N] = A[M,K] @ B[K,N] (+ bias)
// Tile 128x128x16, 256 threads (8 warps 2x4), warp tile 64x32, m16n8k8.
// 4-stage cp.async pipeline, fp32 in smem, tf32 cvt at fragment load.
// K multiple of 16; A reads always in-bounds; B zfilled by (k<KB, col<NB).
// ---------------------------------------------------------------------------
#define STAGES 4
#define ASTR   20     // 16+4 pad (floats); row offset 80B = 5*16 (cp.async ok)
#define BSTR   136    // 128+8 pad; k-row offset 544B = 34*16; frag conflict-free
#define A_FLTS (128 * ASTR)            // 2560
#define B_FLTS (16 * BSTR)             // 2176
#define STAGE_FLTS (A_FLTS + B_FLTS)   // 4736
#define SMEM_BYTES (STAGES * STAGE_FLTS * 4)   // 75776

template <bool HAS_BIAS>
__device__ __forceinline__ void gemm_body(
    const float* __restrict__ A, const float* __restrict__ B,
    float* __restrict__ C, const float* __restrict__ bias,
    int K, int lda, int ldb, int ldc, int NB, int KB, int Nstore,
    int row0, int col0)
{
    extern __shared__ float smem[];

    const int tid  = threadIdx.x;
    const int wid  = tid >> 5;
    const int lane = tid & 31;
    const int gp   = lane >> 2;
    const int tg   = lane & 3;
    const int warp_m = (wid & 1) * 64;
    const int warp_n = (wid >> 1) * 32;

    // per-thread load slots (2 each for A and B)
    const int arow0 = tid >> 2,           ak4 = (tid & 3) << 2;      // + i*64 rows
    const int bkr0  = tid >> 5,           bc4 = (tid & 31) << 2;     // + i*8  k-rows

    auto issue_stage = [&](int s, int k0) {
        float* sA = smem + s * STAGE_FLTS;
        float* sB = sA + A_FLTS;
        #pragma unroll
        for (int i = 0; i < 2; i++) {
            // A: 128 rows x 16 k, 16B per thread-slot
            int arow = arow0 + i * 64;
            CP_ASYNC16(smem_u32(sA + arow * ASTR + ak4),
                       A + (size_t)(row0 + arow) * lda + k0 + ak4, 16);
            // B: 16 k-rows x 128 cols, zfill at ragged edges
            int gk = k0 + bkr0 + i * 8;
            int gc = col0 + bc4;
            int rem = NB - gc;
            int valid = (gk < KB) ? (rem >= 4 ? 16 : (rem > 0 ? rem * 4 : 0)) : 0;
            int gkc = (gk < KB) ? gk : 0;
            int gcc = (valid > 0) ? gc : 0;
            CP_ASYNC16(smem_u32(sB + (bkr0 + i * 8) * BSTR + bc4),
                       B + (size_t)gkc * ldb + gcc, valid);
        }
        CP_COMMIT();
    };

    float acc[4][4][4];
    #pragma unroll
    for (int mt = 0; mt < 4; mt++)
        #pragma unroll
        for (int nt = 0; nt < 4; nt++)
            #pragma unroll
            for (int r = 0; r < 4; r++) acc[mt][nt][r] = 0.f;

    const int k_tiles = K / 16;
    int fetch = 0;
    for (; fetch < STAGES - 1; fetch++)          // k_tiles >= 32 always here
        issue_stage(fetch, fetch * 16);
    CP_WAIT(STAGES - 2);
    __syncthreads();

    int cur = 0;
    for (int it = 0; it < k_tiles; it++) {
        if (fetch < k_tiles) {
            issue_stage(fetch % STAGES, fetch * 16);
            fetch++;
        } else {
            CP_COMMIT();                          // empty group keeps counts aligned
        }

        const float* sA = smem + cur * STAGE_FLTS;
        const float* sB = sA + A_FLTS;
        #pragma unroll
        for (int ks = 0; ks < 2; ks++) {
            unsigned af[4][4], bf[4][2];
            #pragma unroll
            for (int mt = 0; mt < 4; mt++) {
                const float* base = sA + (warp_m + mt * 16 + gp) * ASTR + ks * 8 + tg;
                af[mt][0] = f2tf(base[0]);
                af[mt][1] = f2tf(base[8 * ASTR]);
                af[mt][2] = f2tf(base[4]);
                af[mt][3] = f2tf(base[8 * ASTR + 4]);
            }
            #pragma unroll
            for (int nt = 0; nt < 4; nt++) {
                const float* base = sB + (ks * 8 + tg) * BSTR + warp_n + nt * 8 + gp;
                bf[nt][0] = f2tf(base[0]);
                bf[nt][1] = f2tf(base[4 * BSTR]);
            }
            #pragma unroll
            for (int mt = 0; mt < 4; mt++)
                #pragma unroll
                for (int nt = 0; nt < 4; nt++) {
                    asm volatile(
                        "mma.sync.aligned.m16n8k8.row.col.f32.tf32.tf32.f32 "
                        "{%0,%1,%2,%3}, {%4,%5,%6,%7}, {%8,%9}, {%0,%1,%2,%3};"
                        : "+f"(acc[mt][nt][0]), "+f"(acc[mt][nt][1]),
                          "+f"(acc[mt][nt][2]), "+f"(acc[mt][nt][3])
                        : "r"(af[mt][0]), "r"(af[mt][1]),
                          "r"(af[mt][2]), "r"(af[mt][3]),
                          "r"(bf[nt][0]), "r"(bf[nt][1]));
                }
        }

        CP_WAIT(STAGES - 2);
        __syncthreads();
        cur = (cur + 1) % STAGES;
    }

    // Epilogue: c0,c1 -> (row gp, cols 2tg,2tg+1); c2,c3 -> row gp+8
    const bool full = (col0 + 128) <= Nstore;
    #pragma unroll
    for (int mt = 0; mt < 4; mt++) {
        #pragma unroll
        for (int half = 0; half < 2; half++) {
            int r = row0 + warp_m + mt * 16 + gp + half * 8;
            float* crow = C + (size_t)r * ldc;
            #pragma unroll
            for (int nt = 0; nt < 4; nt++) {
                int c  = col0 + warp_n + nt * 8 + tg * 2;
                float v0 = acc[mt][nt][half * 2 + 0];
                float v1 = acc[mt][nt][half * 2 + 1];
                if (full) {
                    if (HAS_BIAS) { v0 += bias[c]; v1 += bias[c + 1]; }
                    *(float2*)(crow + c) = make_float2(v0, v1);
                } else {
                    if (c < Nstore) {
                        if (HAS_BIAS) v0 += bias[c];
                        crow[c] = v0;
                    }
                    if (c + 1 < Nstore) {
                        if (HAS_BIAS) v1 += bias[c + 1];
                        crow[c + 1] = v1;
                    }
                }
            }
        }
    }
}

// Merged GEMM1 + GEMM2 (independent; one launch => one ragged wave-tail)
__global__ __launch_bounds__(256, 2) void qkv_gemm_kernel(
    const float* __restrict__ query, const float* __restrict__ value,
    const float* __restrict__ qk_w,  const float* __restrict__ v_w,
    float* __restrict__ QK, float* __restrict__ V)
{
    const int x = blockIdx.x;
    const int row0 = blockIdx.y * 128;
    if (x < 19) {   // GEMM1: QK = query @ qk_w  [16384,512]@[512,2352]
        gemm_body<false>(query, qk_w, QK, nullptr,
                         512, 512, QKC, QKC, QKC, 512, QKC,
                         row0, x * 128);
    } else {        // GEMM2: V = value @ v_w    [16384,512]@[512,1176] -> pad 1184
        gemm_body<false>(value, v_w, V, nullptr,
                         512, 512, DH, VSTRIDE, DH, 512, VSTRIDE,
                         row0, (x - 19) * 128);
    }
}

// GEMM3: out = V @ lin_w + b   [16384,1184(pad)]@[1176,512]; N=512 unguarded
__global__ __launch_bounds__(256, 2) void out_gemm_kernel(
    const float* __restrict__ V, const float* __restrict__ lin_w,
    float* __restrict__ out, const float* __restrict__ lin_b)
{
    gemm_body<true>(V, lin_w, out, lin_b,
                    VSTRIDE, VSTRIDE, DMODEL, DMODEL, DMODEL, DH, DMODEL,
                    blockIdx.y * 128, blockIdx.x * 128);
}

// ---------------------------------------------------------------------------
// Tiny per-frame attention: one warp per (m, h) unit, 8 warps per block.
// In-place update of g_V[m, h*147+3 .. h*147+146] (dims 0..2 untouched).
// ---------------------------------------------------------------------------
__global__ __launch_bounds__(256) void attn_kernel(
    const float* __restrict__ QK, float* __restrict__ V)
{
    const int warp = threadIdx.x >> 5;
    const int lane = threadIdx.x & 31;
    const int f = blockIdx.x * 8 + warp;
    const int m = f >> 3;
    const int h = f & 7;

    __shared__ float sq[8][144];
    __shared__ float sk[8][144];
    __shared__ float sv[8][144];
    __shared__ float sp[8][24][25];

    float* q = sq[warp];
    float* k = sk[warp];
    float* v = sv[warp];
    float (*p)[25] = sp[warp];

    const float* qrow = QK + (size_t)m * QKC + h * DEPTH + 3;
    const float* krow = QK + (size_t)m * QKC + DH + h * DEPTH + 3;
    float*       vrow = V  + (size_t)m * VSTRIDE + h * DEPTH + 3;

    for (int i = lane; i < 144; i += 32) {
        q[i] = qrow[i];
        k[i] = krow[i];
        v[i] = vrow[i];
    }
    __syncwarp();

    const float scale = 0.4082482904638630f;  // 1/sqrt(6)
    for (int e = lane; e < 576; e += 32) {
        int r = e / 24, c = e % 24;
        float s = 0.f;
        #pragma unroll
        for (int d = 0; d < 6; d++) s = fmaf(q[r * 6 + d], k[c * 6 + d], s);
        p[r][c] = s * scale;
    }
    __syncwarp();

    if (lane < 24) {
        float mx = -1e30f;
        #pragma unroll
        for (int c = 0; c < 24; c++) mx = fmaxf(mx, p[lane][c]);
        float sum = 0.f;
        #pragma unroll
        for (int c = 0; c < 24; c++) {
            float e = __expf(p[lane][c] - mx);
            p[lane][c] = e;
            sum += e;
        }
        float inv = 1.0f / sum;
        #pragma unroll
        for (int c = 0; c < 24; c++) p[lane][c] *= inv;
    }
    __syncwarp();

    if (lane == 0) {
        p[0][6]  = (p[0][6]  + p[0][3])  * 0.5f;
        p[6][0]  = (p[6][0]  + p[3][0])  * 0.5f;
        p[0][9]  = (p[0][9]  + p[0][6])  * 0.5f;
        p[9][0]  = (p[9][0]  + p[6][0])  * 0.5f;
        p[0][12] = (p[0][12] + p[0][9])  * 0.5f;
        p[12][0] = (p[12][0] + p[9][0])  * 0.5f;
        p[0][13] = (p[0][13] + p[0][9])  * 0.5f;
        p[13][0] = (p[13][0] + p[9][0])  * 0.5f;
        p[0][14] = (p[0][14] + p[0][9])  * 0.5f;
        p[14][0] = (p[14][0] + p[9][0])  * 0.5f;
        p[0][16] = (p[0][16] + p[0][13]) * 0.5f;
        p[16][0] = (p[16][0] + p[13][0]) * 0.5f;
        p[0][17] = (p[0][17] + p[0][14]) * 0.5f;
        p[17][0] = (p[17][0] + p[14][0]) * 0.5f;
        p[0][15] = (p[0][15] + p[0][12]) * 0.5f;
        p[15][0] = (p[15][0] + p[12][0]) * 0.5f;
    }
    __syncwarp();

    for (int e = lane; e < 144; e += 32) {
        int r = e / 6, d = e % 6;
        float s = 0.f;
        #pragma unroll
        for (int kk = 0; kk < 24; kk++) s = fmaf(p[r][kk], v[kk * 6 + d], s);
        vrow[e] = s;
    }
}

// ---------------------------------------------------------------------------
// Entry point
// ---------------------------------------------------------------------------
extern "C" void kernel_launch(void* const* d_in, const int* in_sizes, int n_in,
                              void* d_out, int out_size)
{
    const float* query = (const float*)d_in[0];
    // d_in[1] = key: intentionally unused (reference ignores it)
    const float* value = (const float*)d_in[2];
    const float* qk_w  = (const float*)d_in[3];
    const float* v_w   = (const float*)d_in[4];
    const float* lin_w = (const float*)d_in[5];
    const float* lin_b = (const float*)d_in[6];
    float* out = (float*)d_out;

    static float* QK = nullptr;
    static float* V  = nullptr;
    if (!QK) {
        cudaGetSymbolAddress((void**)&QK, g_QK);
        cudaGetSymbolAddress((void**)&V,  g_V);
        cudaFuncSetAttribute(qkv_gemm_kernel,
                             cudaFuncAttributeMaxDynamicSharedMemorySize, SMEM_BYTES);
        cudaFuncSetAttribute(out_gemm_kernel,
                             cudaFuncAttributeMaxDynamicSharedMemorySize, SMEM_BYTES);
    }

    dim3 blk(256);

    // GEMM1 + GEMM2 fused launch (19 + 10 column tiles)
    qkv_gemm_kernel<<<dim3(29, MROWS / 128), blk, SMEM_BYTES>>>(
        query, value, qk_w, v_w, QK, V);

    // Tiny attention, in-place update of V (one warp per (m,h))
    attn_kernel<<<(MROWS * HEADS) / 8, 256>>>(QK, V);

    // GEMM3
    out_gemm_kernel<<<dim3(DMODEL / 128, MROWS / 128), blk, SMEM_BYTES>>>(
        V, lin_w, out, lin_b);
}